// round 1
// baseline (speedup 1.0000x reference)
#include <cuda_runtime.h>
#include <cuda_bf16.h>
#include <cstdint>

#define N_NODES 50000
#define DIM 128
#define DOUT 64

// Scratch (no allocations allowed -> __device__ globals)
__device__ float g_deg[N_NODES];
__device__ float g_dinv[N_NODES];
__device__ float g_agg0[(size_t)N_NODES * DIM]; // A @ x
__device__ float g_h[(size_t)N_NODES * DIM];    // relu(agg0 @ W1 + b1)
__device__ float g_agg2[(size_t)N_NODES * DIM]; // A @ h

// ---------------------------------------------------------------------------
// Degree: deg[dst] += 1 over all edges
// ---------------------------------------------------------------------------
__global__ void deg_kernel(const int* __restrict__ dst, int E) {
    int e = blockIdx.x * blockDim.x + threadIdx.x;
    if (e < E) {
        atomicAdd(&g_deg[dst[e]], 1.0f);
    }
}

__global__ void dinv_kernel(int n) {
    int i = blockIdx.x * blockDim.x + threadIdx.x;
    if (i < n) {
        float d = g_deg[i];
        g_dinv[i] = (d > 0.0f) ? rsqrtf(d) : 0.0f;
    }
}

// ---------------------------------------------------------------------------
// Scatter: agg[dst] += feat[src] * (dinv[src]*dinv[dst]),  128 floats/edge.
// One warp per edge; lane handles one float4; red.global.add.v4.f32 scatter.
// ---------------------------------------------------------------------------
__global__ __launch_bounds__(256) void scatter_kernel(
    const float* __restrict__ feat,
    const int* __restrict__ src,
    const int* __restrict__ dst,
    const float* __restrict__ dinv,
    float* __restrict__ agg,
    int E)
{
    int widx = (int)((blockIdx.x * (unsigned)blockDim.x + threadIdx.x) >> 5);
    int lane = threadIdx.x & 31;
    if (widx >= E) return;

    int s = __ldg(src + widx);
    int d = __ldg(dst + widx);
    float nrm = __ldg(dinv + s) * __ldg(dinv + d);

    float4 v = ((const float4*)(feat + (size_t)s * DIM))[lane];
    float* p = agg + (size_t)d * DIM + lane * 4;
    asm volatile("red.global.add.v4.f32 [%0], {%1, %2, %3, %4};" ::
                 "l"(p),
                 "f"(v.x * nrm), "f"(v.y * nrm), "f"(v.z * nrm), "f"(v.w * nrm)
                 : "memory");
}

// ---------------------------------------------------------------------------
// GEMM 1: h = relu(A @ W + b),  A: [M,128], W: [128,128] row-major.
// Block: 256 threads = 8 warps; block tile 32 rows x 128 cols.
// Warp w -> rows w*4..w*4+3; lane -> cols lane*4..lane*4+3.
// ---------------------------------------------------------------------------
__global__ __launch_bounds__(256) void gemm_relu_kernel(
    const float* __restrict__ A,
    const float* __restrict__ W,
    const float* __restrict__ bias,
    float* __restrict__ out,
    int M)
{
    __shared__ float sA[32][DIM];
    int warp = threadIdx.x >> 5;
    int lane = threadIdx.x & 31;
    int rowBase = blockIdx.x * 32;

    // Cooperative load of A tile (32 rows x 128 cols) as float4s
    for (int i = threadIdx.x; i < 32 * 32; i += 256) {
        int r = i >> 5, c4 = i & 31;
        int gr = rowBase + r;
        float4 v = make_float4(0.f, 0.f, 0.f, 0.f);
        if (gr < M) v = ((const float4*)(A + (size_t)gr * DIM))[c4];
        ((float4*)sA[r])[c4] = v;
    }
    __syncthreads();

    int r0 = warp * 4;
    float4 acc0 = make_float4(0.f, 0.f, 0.f, 0.f);
    float4 acc1 = make_float4(0.f, 0.f, 0.f, 0.f);
    float4 acc2 = make_float4(0.f, 0.f, 0.f, 0.f);
    float4 acc3 = make_float4(0.f, 0.f, 0.f, 0.f);

#pragma unroll 4
    for (int k = 0; k < DIM; k++) {
        float4 w = ((const float4*)(W + (size_t)k * DIM))[lane];
        float a0 = sA[r0 + 0][k];
        float a1 = sA[r0 + 1][k];
        float a2 = sA[r0 + 2][k];
        float a3 = sA[r0 + 3][k];
        acc0.x += a0 * w.x; acc0.y += a0 * w.y; acc0.z += a0 * w.z; acc0.w += a0 * w.w;
        acc1.x += a1 * w.x; acc1.y += a1 * w.y; acc1.z += a1 * w.z; acc1.w += a1 * w.w;
        acc2.x += a2 * w.x; acc2.y += a2 * w.y; acc2.z += a2 * w.z; acc2.w += a2 * w.w;
        acc3.x += a3 * w.x; acc3.y += a3 * w.y; acc3.z += a3 * w.z; acc3.w += a3 * w.w;
    }

    float4 b = ((const float4*)bias)[lane];
    float4 accs[4] = {acc0, acc1, acc2, acc3};
#pragma unroll
    for (int r = 0; r < 4; r++) {
        int row = rowBase + r0 + r;
        if (row < M) {
            float4 res;
            res.x = fmaxf(accs[r].x + b.x, 0.f);
            res.y = fmaxf(accs[r].y + b.y, 0.f);
            res.z = fmaxf(accs[r].z + b.z, 0.f);
            res.w = fmaxf(accs[r].w + b.w, 0.f);
            ((float4*)(out + (size_t)row * DIM))[lane] = res;
        }
    }
}

// ---------------------------------------------------------------------------
// GEMM 2: mu = A @ Wmu + bmu (lanes 0..15), ls = A @ Wls + bls (lanes 16..31)
// A: [M,128]. Wmu/Wls: [128,64] row-major. Outputs [M,64] each, concatenated
// in d_out: mu at [0, M*64), logstd at [M*64, 2*M*64).
// ---------------------------------------------------------------------------
__global__ __launch_bounds__(256) void gemm_out_kernel(
    const float* __restrict__ A,
    const float* __restrict__ Wmu,
    const float* __restrict__ bmu,
    const float* __restrict__ Wls,
    const float* __restrict__ bls,
    float* __restrict__ out,
    int M)
{
    __shared__ float sA[32][DIM];
    int warp = threadIdx.x >> 5;
    int lane = threadIdx.x & 31;
    int rowBase = blockIdx.x * 32;

    for (int i = threadIdx.x; i < 32 * 32; i += 256) {
        int r = i >> 5, c4 = i & 31;
        int gr = rowBase + r;
        float4 v = make_float4(0.f, 0.f, 0.f, 0.f);
        if (gr < M) v = ((const float4*)(A + (size_t)gr * DIM))[c4];
        ((float4*)sA[r])[c4] = v;
    }
    __syncthreads();

    const float* Wsel = (lane < 16) ? Wmu : Wls;
    const float* bsel = (lane < 16) ? bmu : bls;
    float* obase = (lane < 16) ? out : out + (size_t)M * DOUT;
    int c = (lane & 15) * 4;

    int r0 = warp * 4;
    float4 acc0 = make_float4(0.f, 0.f, 0.f, 0.f);
    float4 acc1 = make_float4(0.f, 0.f, 0.f, 0.f);
    float4 acc2 = make_float4(0.f, 0.f, 0.f, 0.f);
    float4 acc3 = make_float4(0.f, 0.f, 0.f, 0.f);

#pragma unroll 4
    for (int k = 0; k < DIM; k++) {
        float4 w = *(const float4*)(Wsel + (size_t)k * DOUT + c);
        float a0 = sA[r0 + 0][k];
        float a1 = sA[r0 + 1][k];
        float a2 = sA[r0 + 2][k];
        float a3 = sA[r0 + 3][k];
        acc0.x += a0 * w.x; acc0.y += a0 * w.y; acc0.z += a0 * w.z; acc0.w += a0 * w.w;
        acc1.x += a1 * w.x; acc1.y += a1 * w.y; acc1.z += a1 * w.z; acc1.w += a1 * w.w;
        acc2.x += a2 * w.x; acc2.y += a2 * w.y; acc2.z += a2 * w.z; acc2.w += a2 * w.w;
        acc3.x += a3 * w.x; acc3.y += a3 * w.y; acc3.z += a3 * w.z; acc3.w += a3 * w.w;
    }

    float4 b = *(const float4*)(bsel + c);
    float4 accs[4] = {acc0, acc1, acc2, acc3};
#pragma unroll
    for (int r = 0; r < 4; r++) {
        int row = rowBase + r0 + r;
        if (row < M) {
            float4 res;
            res.x = accs[r].x + b.x;
            res.y = accs[r].y + b.y;
            res.z = accs[r].z + b.z;
            res.w = accs[r].w + b.w;
            *(float4*)(obase + (size_t)row * DOUT + c) = res;
        }
    }
}

// ---------------------------------------------------------------------------
// Launch
// ---------------------------------------------------------------------------
extern "C" void kernel_launch(void* const* d_in, const int* in_sizes, int n_in,
                              void* d_out, int out_size) {
    const float* x    = (const float*)d_in[0];   // [N, 128]
    const int*   eidx = (const int*)d_in[1];     // [2, E] int32
    const float* w1   = (const float*)d_in[2];   // [128, 128]
    const float* b1   = (const float*)d_in[3];   // [128]
    const float* w_mu = (const float*)d_in[4];   // [128, 64]
    const float* b_mu = (const float*)d_in[5];   // [64]
    const float* w_ls = (const float*)d_in[6];   // [128, 64]
    const float* b_ls = (const float*)d_in[7];   // [64]
    float* out = (float*)d_out;

    int N = in_sizes[0] / DIM;       // 50000
    int E = in_sizes[1] / 2;         // 800000
    const int* src = eidx;
    const int* dst = eidx + E;

    // Zero scratch that is accumulated into (memset nodes are capturable)
    void *p_deg, *p_agg0, *p_agg2;
    cudaGetSymbolAddress(&p_deg, g_deg);
    cudaGetSymbolAddress(&p_agg0, g_agg0);
    cudaGetSymbolAddress(&p_agg2, g_agg2);
    cudaMemsetAsync(p_deg, 0, (size_t)N_NODES * sizeof(float));
    cudaMemsetAsync(p_agg0, 0, (size_t)N_NODES * DIM * sizeof(float));
    cudaMemsetAsync(p_agg2, 0, (size_t)N_NODES * DIM * sizeof(float));

    // Degrees + normalization
    deg_kernel<<<(E + 255) / 256, 256>>>(dst, E);
    dinv_kernel<<<(N + 255) / 256, 256>>>(N);

    // Layer 1: agg0 = A_norm @ x ; h = relu(agg0 @ W1 + b1)
    {
        float* agg0;
        cudaGetSymbolAddress((void**)&agg0, g_agg0);
        float* h;
        cudaGetSymbolAddress((void**)&h, g_h);
        float* dinv;
        cudaGetSymbolAddress((void**)&dinv, g_dinv);

        long long warps = E;
        int blocks = (int)((warps * 32 + 255) / 256);
        scatter_kernel<<<blocks, 256>>>(x, src, dst, dinv, agg0, E);

        int gblocks = (N + 31) / 32;
        gemm_relu_kernel<<<gblocks, 256>>>(agg0, w1, b1, h, N);
    }

    // Layer 2: agg2 = A_norm @ h ; mu = agg2@Wmu+bmu ; ls = agg2@Wls+bls
    {
        float* agg2;
        cudaGetSymbolAddress((void**)&agg2, g_agg2);
        float* h;
        cudaGetSymbolAddress((void**)&h, g_h);
        float* dinv;
        cudaGetSymbolAddress((void**)&dinv, g_dinv);

        long long warps = E;
        int blocks = (int)((warps * 32 + 255) / 256);
        scatter_kernel<<<blocks, 256>>>(h, src, dst, dinv, agg2, E);

        int gblocks = (N + 31) / 32;
        gemm_out_kernel<<<gblocks, 256>>>(agg2, w_mu, b_mu, w_ls, b_ls, out, N);
    }
}

// round 2
// speedup vs baseline: 1.7051x; 1.7051x over previous
#include <cuda_runtime.h>
#include <cuda_bf16.h>
#include <cstdint>

#define N_NODES 50000
#define MAX_E   800000
#define DIM     128
#define DOUT    64

// Scratch (no allocations allowed -> __device__ globals)
__device__ int   g_deg[N_NODES];
__device__ int   g_rowptr[N_NODES + 1];
__device__ int   g_cursor[N_NODES];
__device__ int   g_bsum[256];
__device__ int   g_boff[256];
__device__ float g_dinv[N_NODES];
__device__ int   g_esrc[MAX_E];
__device__ float g_enorm[MAX_E];
__device__ float g_agg0[(size_t)N_NODES * DIM]; // A @ x
__device__ float g_h[(size_t)N_NODES * DIM];    // relu(agg0 @ W1 + b1)
__device__ float g_agg2[(size_t)N_NODES * DIM]; // A @ h

// ---------------------------------------------------------------------------
// Histogram over dst
// ---------------------------------------------------------------------------
__global__ void hist_kernel(const int* __restrict__ dst, int E) {
    int e = blockIdx.x * blockDim.x + threadIdx.x;
    if (e < E) atomicAdd(&g_deg[dst[e]], 1);
}

// ---------------------------------------------------------------------------
// 3-phase exclusive scan of g_deg -> g_rowptr
// ---------------------------------------------------------------------------
__global__ void scan1_kernel(int N) {
    __shared__ int tmp[256];
    int t = threadIdx.x;
    int i = blockIdx.x * 256 + t;
    int v = (i < N) ? g_deg[i] : 0;
    tmp[t] = v;
    __syncthreads();
#pragma unroll
    for (int off = 1; off < 256; off <<= 1) {
        int x = (t >= off) ? tmp[t - off] : 0;
        __syncthreads();
        tmp[t] += x;
        __syncthreads();
    }
    if (i < N) g_rowptr[i] = tmp[t] - v;           // block-local exclusive
    if (t == 255) g_bsum[blockIdx.x] = tmp[255];
}

__global__ void scan2_kernel(int nb) {
    __shared__ int tmp[256];
    int t = threadIdx.x;
    int v = (t < nb) ? g_bsum[t] : 0;
    tmp[t] = v;
    __syncthreads();
#pragma unroll
    for (int off = 1; off < 256; off <<= 1) {
        int x = (t >= off) ? tmp[t - off] : 0;
        __syncthreads();
        tmp[t] += x;
        __syncthreads();
    }
    g_boff[t] = tmp[t] - v;                        // exclusive
}

__global__ void scan3_kernel(int N, int E) {
    int i = blockIdx.x * 256 + threadIdx.x;
    if (i < N) {
        g_rowptr[i] += g_boff[blockIdx.x];
        int d = g_deg[i];
        g_dinv[i] = (d > 0) ? rsqrtf((float)d) : 0.0f;
    }
    if (i == 0) g_rowptr[N] = E;
}

// ---------------------------------------------------------------------------
// Fill edge list grouped by dst: (src, dinv[src]*dinv[dst])
// ---------------------------------------------------------------------------
__global__ void fill_kernel(const int* __restrict__ src,
                            const int* __restrict__ dst, int E) {
    int e = blockIdx.x * blockDim.x + threadIdx.x;
    if (e >= E) return;
    int s = src[e];
    int d = dst[e];
    int pos = g_rowptr[d] + atomicAdd(&g_cursor[d], 1);
    g_esrc[pos] = s;
    g_enorm[pos] = g_dinv[s] * g_dinv[d];
}

// ---------------------------------------------------------------------------
// Aggregation: out[n] = sum_{edges e with dst=n} feat[src_e] * norm_e
// One warp per node; lane handles one float4 (128 floats / 32 lanes).
// No atomics, no pre-zeroing needed.
// ---------------------------------------------------------------------------
__global__ __launch_bounds__(256) void agg_kernel(
    const float* __restrict__ feat,
    float* __restrict__ out,
    int N)
{
    int node = blockIdx.x * 8 + (threadIdx.x >> 5);
    int lane = threadIdx.x & 31;
    if (node >= N) return;

    int beg = g_rowptr[node];
    int end = g_rowptr[node + 1];

    float4 acc = make_float4(0.f, 0.f, 0.f, 0.f);
    const float4* f4 = (const float4*)feat;

    int j = beg;
    for (; j + 2 <= end; j += 2) {
        int   s0 = __ldg(g_esrc + j);
        float w0 = __ldg(g_enorm + j);
        int   s1 = __ldg(g_esrc + j + 1);
        float w1 = __ldg(g_enorm + j + 1);
        float4 v0 = f4[(size_t)s0 * 32 + lane];
        float4 v1 = f4[(size_t)s1 * 32 + lane];
        acc.x += v0.x * w0; acc.y += v0.y * w0; acc.z += v0.z * w0; acc.w += v0.w * w0;
        acc.x += v1.x * w1; acc.y += v1.y * w1; acc.z += v1.z * w1; acc.w += v1.w * w1;
    }
    if (j < end) {
        int   s0 = __ldg(g_esrc + j);
        float w0 = __ldg(g_enorm + j);
        float4 v0 = f4[(size_t)s0 * 32 + lane];
        acc.x += v0.x * w0; acc.y += v0.y * w0; acc.z += v0.z * w0; acc.w += v0.w * w0;
    }
    ((float4*)out)[(size_t)node * 32 + lane] = acc;
}

// ---------------------------------------------------------------------------
// GEMM 1: h = relu(A @ W + b),  A: [M,128], W: [128,128] row-major.
// Block: 256 thr = 8 warps; tile 64 rows x 128 cols; thread: 8 rows x 4 cols.
// ---------------------------------------------------------------------------
__global__ __launch_bounds__(256) void gemm_relu_kernel(
    const float* __restrict__ A,
    const float* __restrict__ W,
    const float* __restrict__ bias,
    float* __restrict__ out,
    int M)
{
    __shared__ float sA[64][DIM];
    int warp = threadIdx.x >> 5;
    int lane = threadIdx.x & 31;
    int rowBase = blockIdx.x * 64;

    // Cooperative load of A tile (64 rows x 128 cols) as float4s
    for (int i = threadIdx.x; i < 64 * 32; i += 256) {
        int r = i >> 5, c4 = i & 31;
        int gr = rowBase + r;
        float4 v = make_float4(0.f, 0.f, 0.f, 0.f);
        if (gr < M) v = ((const float4*)(A + (size_t)gr * DIM))[c4];
        ((float4*)sA[r])[c4] = v;
    }
    __syncthreads();

    int r0 = warp * 8;
    float4 acc[8];
#pragma unroll
    for (int r = 0; r < 8; r++) acc[r] = make_float4(0.f, 0.f, 0.f, 0.f);

#pragma unroll 4
    for (int k = 0; k < DIM; k += 2) {
        float4 w0 = ((const float4*)(W + (size_t)k * DIM))[lane];
        float4 w1 = ((const float4*)(W + (size_t)(k + 1) * DIM))[lane];
#pragma unroll
        for (int r = 0; r < 8; r++) {
            float2 a = *(const float2*)&sA[r0 + r][k];
            acc[r].x += a.x * w0.x; acc[r].y += a.x * w0.y;
            acc[r].z += a.x * w0.z; acc[r].w += a.x * w0.w;
            acc[r].x += a.y * w1.x; acc[r].y += a.y * w1.y;
            acc[r].z += a.y * w1.z; acc[r].w += a.y * w1.w;
        }
    }

    float4 b = ((const float4*)bias)[lane];
#pragma unroll
    for (int r = 0; r < 8; r++) {
        int row = rowBase + r0 + r;
        if (row < M) {
            float4 res;
            res.x = fmaxf(acc[r].x + b.x, 0.f);
            res.y = fmaxf(acc[r].y + b.y, 0.f);
            res.z = fmaxf(acc[r].z + b.z, 0.f);
            res.w = fmaxf(acc[r].w + b.w, 0.f);
            ((float4*)(out + (size_t)row * DIM))[lane] = res;
        }
    }
}

// ---------------------------------------------------------------------------
// GEMM 2: mu = A @ Wmu + bmu (lanes 0..15), ls = A @ Wls + bls (lanes 16..31)
// Outputs [M,64] each, concatenated: mu at [0, M*64), logstd after.
// ---------------------------------------------------------------------------
__global__ __launch_bounds__(256) void gemm_out_kernel(
    const float* __restrict__ A,
    const float* __restrict__ Wmu,
    const float* __restrict__ bmu,
    const float* __restrict__ Wls,
    const float* __restrict__ bls,
    float* __restrict__ out,
    int M)
{
    __shared__ float sA[64][DIM];
    int warp = threadIdx.x >> 5;
    int lane = threadIdx.x & 31;
    int rowBase = blockIdx.x * 64;

    for (int i = threadIdx.x; i < 64 * 32; i += 256) {
        int r = i >> 5, c4 = i & 31;
        int gr = rowBase + r;
        float4 v = make_float4(0.f, 0.f, 0.f, 0.f);
        if (gr < M) v = ((const float4*)(A + (size_t)gr * DIM))[c4];
        ((float4*)sA[r])[c4] = v;
    }
    __syncthreads();

    const float* Wsel = (lane < 16) ? Wmu : Wls;
    const float* bsel = (lane < 16) ? bmu : bls;
    float* obase = (lane < 16) ? out : out + (size_t)M * DOUT;
    int c = (lane & 15) * 4;

    int r0 = warp * 8;
    float4 acc[8];
#pragma unroll
    for (int r = 0; r < 8; r++) acc[r] = make_float4(0.f, 0.f, 0.f, 0.f);

#pragma unroll 4
    for (int k = 0; k < DIM; k += 2) {
        float4 w0 = *(const float4*)(Wsel + (size_t)k * DOUT + c);
        float4 w1 = *(const float4*)(Wsel + (size_t)(k + 1) * DOUT + c);
#pragma unroll
        for (int r = 0; r < 8; r++) {
            float2 a = *(const float2*)&sA[r0 + r][k];
            acc[r].x += a.x * w0.x; acc[r].y += a.x * w0.y;
            acc[r].z += a.x * w0.z; acc[r].w += a.x * w0.w;
            acc[r].x += a.y * w1.x; acc[r].y += a.y * w1.y;
            acc[r].z += a.y * w1.z; acc[r].w += a.y * w1.w;
        }
    }

    float4 b = *(const float4*)(bsel + c);
#pragma unroll
    for (int r = 0; r < 8; r++) {
        int row = rowBase + r0 + r;
        if (row < M) {
            float4 res;
            res.x = acc[r].x + b.x;
            res.y = acc[r].y + b.y;
            res.z = acc[r].z + b.z;
            res.w = acc[r].w + b.w;
            *(float4*)(obase + (size_t)row * DOUT + c) = res;
        }
    }
}

// ---------------------------------------------------------------------------
// Launch
// ---------------------------------------------------------------------------
extern "C" void kernel_launch(void* const* d_in, const int* in_sizes, int n_in,
                              void* d_out, int out_size) {
    const float* x    = (const float*)d_in[0];   // [N, 128]
    const int*   eidx = (const int*)d_in[1];     // [2, E] int32
    const float* w1   = (const float*)d_in[2];   // [128, 128]
    const float* b1   = (const float*)d_in[3];   // [128]
    const float* w_mu = (const float*)d_in[4];   // [128, 64]
    const float* b_mu = (const float*)d_in[5];   // [64]
    const float* w_ls = (const float*)d_in[6];   // [128, 64]
    const float* b_ls = (const float*)d_in[7];   // [64]
    float* out = (float*)d_out;

    int N = in_sizes[0] / DIM;       // 50000
    int E = in_sizes[1] / 2;         // 800000
    const int* src = eidx;
    const int* dst = eidx + E;

    // Zero histogram + cursors
    void *p_deg, *p_cur;
    cudaGetSymbolAddress(&p_deg, g_deg);
    cudaGetSymbolAddress(&p_cur, g_cursor);
    cudaMemsetAsync(p_deg, 0, (size_t)N_NODES * sizeof(int));
    cudaMemsetAsync(p_cur, 0, (size_t)N_NODES * sizeof(int));

    float *agg0, *h, *agg2;
    cudaGetSymbolAddress((void**)&agg0, g_agg0);
    cudaGetSymbolAddress((void**)&h, g_h);
    cudaGetSymbolAddress((void**)&agg2, g_agg2);

    int eblocks = (E + 255) / 256;
    int nblocks = (N + 255) / 256;   // 196

    // CSR build
    hist_kernel<<<eblocks, 256>>>(dst, E);
    scan1_kernel<<<nblocks, 256>>>(N);
    scan2_kernel<<<1, 256>>>(nblocks);
    scan3_kernel<<<nblocks, 256>>>(N, E);
    fill_kernel<<<eblocks, 256>>>(src, dst, E);

    int ablocks = (N + 7) / 8;       // warp per node
    int gblocks = (N + 63) / 64;

    // Layer 1
    agg_kernel<<<ablocks, 256>>>(x, agg0, N);
    gemm_relu_kernel<<<gblocks, 256>>>(agg0, w1, b1, h, N);

    // Layer 2
    agg_kernel<<<ablocks, 256>>>(h, agg2, N);
    gemm_out_kernel<<<gblocks, 256>>>(agg2, w_mu, b_mu, w_ls, b_ls, out, N);
}

// round 13
// speedup vs baseline: 1.8400x; 1.0791x over previous
#include <cuda_runtime.h>
#include <cuda_fp16.h>
#include <cstdint>

#define N_NODES 50000
#define MAX_E   800000
#define DIM     128
#define DOUT    64

// Scratch (no allocations allowed -> __device__ globals)
__device__ int     g_deg[N_NODES];
__device__ int     g_rowptr[N_NODES + 1];
__device__ int     g_cursor[N_NODES];
__device__ int     g_bsum[256];
__device__ int     g_boff[256];
__device__ float   g_dinv[N_NODES];
__device__ int     g_esrc[MAX_E];
__device__ __half2 g_xs[(size_t)N_NODES * (DIM / 2)]; // dinv[n] * x[n], fp16
__device__ __half2 g_hs[(size_t)N_NODES * (DIM / 2)]; // dinv[n] * relu(h[n]), fp16
__device__ float   g_agg0[(size_t)N_NODES * DIM];     // Adj @ xs
__device__ float   g_agg2[(size_t)N_NODES * DIM];     // Adj @ hs

// ---------------------------------------------------------------------------
// Histogram over dst
// ---------------------------------------------------------------------------
__global__ void hist_kernel(const int* __restrict__ dst, int E) {
    int e = blockIdx.x * blockDim.x + threadIdx.x;
    if (e < E) atomicAdd(&g_deg[dst[e]], 1);
}

// ---------------------------------------------------------------------------
// 3-phase exclusive scan of g_deg -> g_rowptr (+ dinv in phase 3)
// ---------------------------------------------------------------------------
__global__ void scan1_kernel(int N) {
    __shared__ int tmp[256];
    int t = threadIdx.x;
    int i = blockIdx.x * 256 + t;
    int v = (i < N) ? g_deg[i] : 0;
    tmp[t] = v;
    __syncthreads();
#pragma unroll
    for (int off = 1; off < 256; off <<= 1) {
        int x = (t >= off) ? tmp[t - off] : 0;
        __syncthreads();
        tmp[t] += x;
        __syncthreads();
    }
    if (i < N) g_rowptr[i] = tmp[t] - v;           // block-local exclusive
    if (t == 255) g_bsum[blockIdx.x] = tmp[255];
}

__global__ void scan2_kernel(int nb) {
    __shared__ int tmp[256];
    int t = threadIdx.x;
    int v = (t < nb) ? g_bsum[t] : 0;
    tmp[t] = v;
    __syncthreads();
#pragma unroll
    for (int off = 1; off < 256; off <<= 1) {
        int x = (t >= off) ? tmp[t - off] : 0;
        __syncthreads();
        tmp[t] += x;
        __syncthreads();
    }
    g_boff[t] = tmp[t] - v;                        // exclusive
}

__global__ void scan3_kernel(int N, int E) {
    int i = blockIdx.x * 256 + threadIdx.x;
    if (i < N) {
        g_rowptr[i] += g_boff[blockIdx.x];
        int d = g_deg[i];
        g_dinv[i] = (d > 0) ? rsqrtf((float)d) : 0.0f;
    }
    if (i == 0) g_rowptr[N] = E;
}

// ---------------------------------------------------------------------------
// Fill edge list grouped by dst: src index only (norm folded into features)
// ---------------------------------------------------------------------------
__global__ void fill_kernel(const int* __restrict__ src,
                            const int* __restrict__ dst, int E) {
    int e = blockIdx.x * blockDim.x + threadIdx.x;
    if (e >= E) return;
    int d = dst[e];
    int pos = g_rowptr[d] + atomicAdd(&g_cursor[d], 1);
    g_esrc[pos] = src[e];
}

// ---------------------------------------------------------------------------
// Prescale: xs[n] = x[n] * dinv[n], fp32 -> fp16. Thread handles 4 floats.
// ---------------------------------------------------------------------------
__global__ void prescale_kernel(const float* __restrict__ x, int N) {
    int i = blockIdx.x * blockDim.x + threadIdx.x;   // over N*32
    if (i >= N * 32) return;
    float s = g_dinv[i >> 5];
    float4 v = ((const float4*)x)[i];
    uint2 u;
    *(__half2*)&u.x = __floats2half2_rn(v.x * s, v.y * s);
    *(__half2*)&u.y = __floats2half2_rn(v.z * s, v.w * s);
    ((uint2*)g_xs)[i] = u;
}

// ---------------------------------------------------------------------------
// Aggregation: out[n] = sum_{edges e with dst=n} feat[src_e]   (fp16 gather,
// fp32 accumulate). One warp per node; lane handles 4 halves (8B).
// ---------------------------------------------------------------------------
__global__ __launch_bounds__(256) void agg_kernel(
    const __half2* __restrict__ feat,
    float* __restrict__ out,
    int N)
{
    int node = blockIdx.x * 8 + (threadIdx.x >> 5);
    int lane = threadIdx.x & 31;
    if (node >= N) return;

    int beg = g_rowptr[node];
    int end = g_rowptr[node + 1];

    float4 acc = make_float4(0.f, 0.f, 0.f, 0.f);
    const uint2* f = (const uint2*)feat;  // row = 32 x uint2 (256B)

    int j = beg;
    for (; j + 4 <= end; j += 4) {
        int s0 = __ldg(g_esrc + j);
        int s1 = __ldg(g_esrc + j + 1);
        int s2 = __ldg(g_esrc + j + 2);
        int s3 = __ldg(g_esrc + j + 3);
        uint2 u0 = __ldg(&f[(size_t)s0 * 32 + lane]);
        uint2 u1 = __ldg(&f[(size_t)s1 * 32 + lane]);
        uint2 u2 = __ldg(&f[(size_t)s2 * 32 + lane]);
        uint2 u3 = __ldg(&f[(size_t)s3 * 32 + lane]);
#pragma unroll
        for (int q = 0; q < 4; q++) {
            uint2 u = (q == 0) ? u0 : (q == 1) ? u1 : (q == 2) ? u2 : u3;
            float2 fa = __half22float2(*(__half2*)&u.x);
            float2 fb = __half22float2(*(__half2*)&u.y);
            acc.x += fa.x; acc.y += fa.y; acc.z += fb.x; acc.w += fb.y;
        }
    }
    for (; j < end; j++) {
        int s0 = __ldg(g_esrc + j);
        uint2 u = __ldg(&f[(size_t)s0 * 32 + lane]);
        float2 fa = __half22float2(*(__half2*)&u.x);
        float2 fb = __half22float2(*(__half2*)&u.y);
        acc.x += fa.x; acc.y += fa.y; acc.z += fb.x; acc.w += fb.y;
    }
    ((float4*)out)[(size_t)node * 32 + lane] = acc;
}

// ---------------------------------------------------------------------------
// GEMM 1: hs = dinv ⊙ relu((dinv ⊙ agg0) @ W + b)  (fp16 output)
// Block: 256 thr = 8 warps; tile 64 rows x 128 cols; thread: 8 rows x 4 cols.
// ---------------------------------------------------------------------------
__global__ __launch_bounds__(256) void gemm_relu_kernel(
    const float* __restrict__ A,
    const float* __restrict__ W,
    const float* __restrict__ bias,
    __half2* __restrict__ outh,
    int M)
{
    __shared__ float sA[64][DIM];
    int warp = threadIdx.x >> 5;
    int lane = threadIdx.x & 31;
    int rowBase = blockIdx.x * 64;

    // Cooperative load of A tile, scaled by dinv[row]
    for (int i = threadIdx.x; i < 64 * 32; i += 256) {
        int r = i >> 5, c4 = i & 31;
        int gr = rowBase + r;
        float4 v = make_float4(0.f, 0.f, 0.f, 0.f);
        if (gr < M) {
            float s = g_dinv[gr];
            v = ((const float4*)(A + (size_t)gr * DIM))[c4];
            v.x *= s; v.y *= s; v.z *= s; v.w *= s;
        }
        ((float4*)sA[r])[c4] = v;
    }
    __syncthreads();

    int r0 = warp * 8;
    float4 acc[8];
#pragma unroll
    for (int r = 0; r < 8; r++) acc[r] = make_float4(0.f, 0.f, 0.f, 0.f);

#pragma unroll 4
    for (int k = 0; k < DIM; k += 2) {
        float4 w0 = ((const float4*)(W + (size_t)k * DIM))[lane];
        float4 w1 = ((const float4*)(W + (size_t)(k + 1) * DIM))[lane];
#pragma unroll
        for (int r = 0; r < 8; r++) {
            float2 a = *(const float2*)&sA[r0 + r][k];
            acc[r].x += a.x * w0.x; acc[r].y += a.x * w0.y;
            acc[r].z += a.x * w0.z; acc[r].w += a.x * w0.w;
            acc[r].x += a.y * w1.x; acc[r].y += a.y * w1.y;
            acc[r].z += a.y * w1.z; acc[r].w += a.y * w1.w;
        }
    }

    float4 b = ((const float4*)bias)[lane];
#pragma unroll
    for (int r = 0; r < 8; r++) {
        int row = rowBase + r0 + r;
        if (row < M) {
            float s = g_dinv[row];
            float rx = fmaxf(acc[r].x + b.x, 0.f) * s;
            float ry = fmaxf(acc[r].y + b.y, 0.f) * s;
            float rz = fmaxf(acc[r].z + b.z, 0.f) * s;
            float rw = fmaxf(acc[r].w + b.w, 0.f) * s;
            uint2 u;
            *(__half2*)&u.x = __floats2half2_rn(rx, ry);
            *(__half2*)&u.y = __floats2half2_rn(rz, rw);
            ((uint2*)outh)[(size_t)row * 32 + lane] = u;
        }
    }
}

// ---------------------------------------------------------------------------
// GEMM 2: mu = (dinv ⊙ A) @ Wmu + bmu (lanes 0..15),
//         ls = (dinv ⊙ A) @ Wls + bls (lanes 16..31)
// Outputs [M,64] each, concatenated: mu at [0, M*64), logstd after.
// ---------------------------------------------------------------------------
__global__ __launch_bounds__(256) void gemm_out_kernel(
    const float* __restrict__ A,
    const float* __restrict__ Wmu,
    const float* __restrict__ bmu,
    const float* __restrict__ Wls,
    const float* __restrict__ bls,
    float* __restrict__ out,
    int M)
{
    __shared__ float sA[64][DIM];
    int warp = threadIdx.x >> 5;
    int lane = threadIdx.x & 31;
    int rowBase = blockIdx.x * 64;

    for (int i = threadIdx.x; i < 64 * 32; i += 256) {
        int r = i >> 5, c4 = i & 31;
        int gr = rowBase + r;
        float4 v = make_float4(0.f, 0.f, 0.f, 0.f);
        if (gr < M) {
            float s = g_dinv[gr];
            v = ((const float4*)(A + (size_t)gr * DIM))[c4];
            v.x *= s; v.y *= s; v.z *= s; v.w *= s;
        }
        ((float4*)sA[r])[c4] = v;
    }
    __syncthreads();

    const float* Wsel = (lane < 16) ? Wmu : Wls;
    const float* bsel = (lane < 16) ? bmu : bls;
    float* obase = (lane < 16) ? out : out + (size_t)M * DOUT;
    int c = (lane & 15) * 4;

    int r0 = warp * 8;
    float4 acc[8];
#pragma unroll
    for (int r = 0; r < 8; r++) acc[r] = make_float4(0.f, 0.f, 0.f, 0.f);

#pragma unroll 4
    for (int k = 0; k < DIM; k += 2) {
        float4 w0 = *(const float4*)(Wsel + (size_t)k * DOUT + c);
        float4 w1 = *(const float4*)(Wsel + (size_t)(k + 1) * DOUT + c);
#pragma unroll
        for (int r = 0; r < 8; r++) {
            float2 a = *(const float2*)&sA[r0 + r][k];
            acc[r].x += a.x * w0.x; acc[r].y += a.x * w0.y;
            acc[r].z += a.x * w0.z; acc[r].w += a.x * w0.w;
            acc[r].x += a.y * w1.x; acc[r].y += a.y * w1.y;
            acc[r].z += a.y * w1.z; acc[r].w += a.y * w1.w;
        }
    }

    float4 b = *(const float4*)(bsel + c);
#pragma unroll
    for (int r = 0; r < 8; r++) {
        int row = rowBase + r0 + r;
        if (row < M) {
            float4 res;
            res.x = acc[r].x + b.x;
            res.y = acc[r].y + b.y;
            res.z = acc[r].z + b.z;
            res.w = acc[r].w + b.w;
            *(float4*)(obase + (size_t)row * DOUT + c) = res;
        }
    }
}

// ---------------------------------------------------------------------------
// Launch
// ---------------------------------------------------------------------------
extern "C" void kernel_launch(void* const* d_in, const int* in_sizes, int n_in,
                              void* d_out, int out_size) {
    const float* x    = (const float*)d_in[0];   // [N, 128]
    const int*   eidx = (const int*)d_in[1];     // [2, E] int32
    const float* w1   = (const float*)d_in[2];   // [128, 128]
    const float* b1   = (const float*)d_in[3];   // [128]
    const float* w_mu = (const float*)d_in[4];   // [128, 64]
    const float* b_mu = (const float*)d_in[5];   // [64]
    const float* w_ls = (const float*)d_in[6];   // [128, 64]
    const float* b_ls = (const float*)d_in[7];   // [64]
    float* out = (float*)d_out;

    int N = in_sizes[0] / DIM;       // 50000
    int E = in_sizes[1] / 2;         // 800000
    const int* src = eidx;
    const int* dst = eidx + E;

    // Zero histogram + cursors
    void *p_deg, *p_cur;
    cudaGetSymbolAddress(&p_deg, g_deg);
    cudaGetSymbolAddress(&p_cur, g_cursor);
    cudaMemsetAsync(p_deg, 0, (size_t)N_NODES * sizeof(int));
    cudaMemsetAsync(p_cur, 0, (size_t)N_NODES * sizeof(int));

    float *agg0, *agg2;
    __half2 *xs, *hs;
    cudaGetSymbolAddress((void**)&agg0, g_agg0);
    cudaGetSymbolAddress((void**)&agg2, g_agg2);
    cudaGetSymbolAddress((void**)&xs, g_xs);
    cudaGetSymbolAddress((void**)&hs, g_hs);

    int eblocks = (E + 255) / 256;
    int nblocks = (N + 255) / 256;   // 196

    // CSR build (+ dinv)
    hist_kernel<<<eblocks, 256>>>(dst, E);
    scan1_kernel<<<nblocks, 256>>>(N);
    scan2_kernel<<<1, 256>>>(nblocks);
    scan3_kernel<<<nblocks, 256>>>(N, E);
    prescale_kernel<<<(N * 32 + 255) / 256, 256>>>(x, N);
    fill_kernel<<<eblocks, 256>>>(src, dst, E);

    int ablocks = (N + 7) / 8;       // warp per node
    int gblocks = (N + 63) / 64;

    // Layer 1
    agg_kernel<<<ablocks, 256>>>(xs, agg0, N);
    gemm_relu_kernel<<<gblocks, 256>>>(agg0, w1, b1, hs, N);

    // Layer 2
    agg_kernel<<<ablocks, 256>>>(hs, agg2, N);
    gemm_out_kernel<<<gblocks, 256>>>(agg2, w_mu, b_mu, w_ls, b_ls, out, N);
}